// round 2
// baseline (speedup 1.0000x reference)
#include <cuda_runtime.h>
#include <cstdint>

#define NROWS 131072
#define DIN   512
#define NH    512
#define DOUT  128
#define NBOUNDS 24   // LEVELS-1 interior boundaries

// ---------------- scratch (static device globals; no allocs allowed) --------
__device__ float g_h0[(size_t)NROWS * NH];
__device__ float g_h1[(size_t)NROWS * NH];
__device__ unsigned g_min_enc[DIN];
__device__ unsigned g_max_enc[DIN];

// ---------------- order-preserving float<->uint encoding for atomics --------
__device__ __forceinline__ unsigned enc_f(float f) {
    unsigned u = __float_as_uint(f);
    return (u & 0x80000000u) ? ~u : (u | 0x80000000u);
}
__device__ __forceinline__ float dec_f(unsigned e) {
    unsigned u = (e & 0x80000000u) ? (e & 0x7FFFFFFFu) : ~e;
    return __uint_as_float(u);
}

// ---------------- packed fp32x2 helpers (sm_103a FFMA2) ---------------------
__device__ __forceinline__ unsigned long long splat2(float x) {
    unsigned long long r;
    asm("mov.b64 %0, {%1, %1};" : "=l"(r) : "f"(x));
    return r;
}
__device__ __forceinline__ void ffma2(unsigned long long& d,
                                      unsigned long long a,
                                      unsigned long long b) {
    asm("fma.rn.f32x2 %0, %1, %2, %3;" : "=l"(d) : "l"(a), "l"(b), "l"(d));
}
__device__ __forceinline__ float2 unpack2(unsigned long long v) {
    float2 f;
    asm("mov.b64 {%0, %1}, %2;" : "=f"(f.x), "=f"(f.y) : "l"(v));
    return f;
}

// ---------------- kernel 1: init column min/max accumulators ----------------
__global__ void init_minmax() {
    int i = threadIdx.x;
    g_min_enc[i] = 0xFFFFFFFFu;  // encodes +inf side
    g_max_enc[i] = 0x00000000u;  // encodes -inf side
}

// ---------------- kernel 2: per-column min/max over 131072 rows -------------
// block = 512 threads (one per column), each block reduces a 512-row slab.
__global__ void colminmax(const float* __restrict__ x) {
    const int col = threadIdx.x;
    const size_t base = (size_t)blockIdx.x * 512 * DIN + col;
    float v0 = x[base];
    float mn = v0, mx = v0;
    for (int r = 1; r < 512; r++) {
        float v = x[base + (size_t)r * DIN];
        mn = fminf(mn, v);
        mx = fmaxf(mx, v);
    }
    atomicMin(&g_min_enc[col], enc_f(mn));
    atomicMax(&g_max_enc[col], enc_f(mx));
}

// ---------------- kernel 3: discretize -> g_h0 ------------------------------
// idx = #{k in 1..24 : bound_k < v}, bound_k = bmin + (bmax-bmin)*(k/25)
// computed with explicit round-to-nearest mul/add (no fma contraction),
// matching the reference's separate multiply+add in fp32.
__global__ void discretize(const float* __restrict__ x) {
    const int col = threadIdx.x;
    const float bmin = dec_f(g_min_enc[col]);
    const float bmax = dec_f(g_max_enc[col]);
    const float range = __fsub_rn(bmax, bmin);
    float bounds[NBOUNDS];
#pragma unroll
    for (int k = 0; k < NBOUNDS; k++) {
        float frac = __fdiv_rn((float)(k + 1), 25.0f);  // folds to exact fp32 const
        bounds[k] = __fadd_rn(bmin, __fmul_rn(range, frac));
    }
    const size_t base = (size_t)blockIdx.x * 512 * DIN + col;
    for (int r = 0; r < 512; r++) {
        float v = x[base + (size_t)r * DIN];
        int idx = 0;
#pragma unroll
        for (int k = 0; k < NBOUNDS; k++) idx += (bounds[k] < v) ? 1 : 0;
        g_h0[base + (size_t)r * DIN] = (float)idx;
    }
}

// ---------------- kernel 4: fused GEMM + bias + relu (fp32, FFMA2) ----------
// C[M,N] = relu(A[M,K] @ W[K,N] + bias[N]); M = 131072 via grid.x, BM=BN=128.
#define BM 128
#define BN 128
#define BK 16

__global__ __launch_bounds__(256, 2)
void gemm_bias_relu(const float* __restrict__ A, const float* __restrict__ W,
                    const float* __restrict__ bias, float* __restrict__ C,
                    int N, int K) {
    __shared__ __align__(16) float As[BK][BM];  // transposed: As[k][m]
    __shared__ __align__(16) float Bs[BK][BN];

    const int tid = threadIdx.x;
    const int tr = tid >> 4;   // 0..15 -> 8 rows each
    const int tc = tid & 15;   // 0..15 -> 8 cols each
    const size_t blockRow = (size_t)blockIdx.x * BM;
    const int blockCol = blockIdx.y * BN;

    const float* Ab = A + blockRow * K;
    const float* Wb = W + blockCol;

    const int aRow = tid >> 2;         // 0..63 (two iterations, +64)
    const int aK   = (tid & 3) << 2;   // 0,4,8,12
    const int bRow = tid >> 5;         // 0..7 (two iterations, +8)
    const int bCol = (tid & 31) << 2;  // 0..124 step 4

    unsigned long long acc[4][8];      // row-pairs (2 fp32) x 8 cols
#pragma unroll
    for (int i = 0; i < 4; i++)
#pragma unroll
        for (int j = 0; j < 8; j++) acc[i][j] = 0ull;

    for (int k0 = 0; k0 < K; k0 += BK) {
#pragma unroll
        for (int i = 0; i < 2; i++) {
            int r = aRow + i * 64;
            float4 v = *reinterpret_cast<const float4*>(Ab + (size_t)r * K + k0 + aK);
            As[aK + 0][r] = v.x; As[aK + 1][r] = v.y;
            As[aK + 2][r] = v.z; As[aK + 3][r] = v.w;
        }
#pragma unroll
        for (int i = 0; i < 2; i++) {
            int r = bRow + i * 8;
            *reinterpret_cast<float4*>(&Bs[r][bCol]) =
                *reinterpret_cast<const float4*>(Wb + (size_t)(k0 + r) * N + bCol);
        }
        __syncthreads();

#pragma unroll
        for (int k = 0; k < BK; k++) {
            unsigned long long a2[4];
#pragma unroll
            for (int i = 0; i < 4; i++)
                a2[i] = *reinterpret_cast<const unsigned long long*>(&As[k][tr * 8 + i * 2]);
            float4 b03 = *reinterpret_cast<const float4*>(&Bs[k][tc * 8]);
            float4 b47 = *reinterpret_cast<const float4*>(&Bs[k][tc * 8 + 4]);
            unsigned long long b2[8];
            b2[0] = splat2(b03.x); b2[1] = splat2(b03.y);
            b2[2] = splat2(b03.z); b2[3] = splat2(b03.w);
            b2[4] = splat2(b47.x); b2[5] = splat2(b47.y);
            b2[6] = splat2(b47.z); b2[7] = splat2(b47.w);
#pragma unroll
            for (int i = 0; i < 4; i++)
#pragma unroll
                for (int j = 0; j < 8; j++) ffma2(acc[i][j], a2[i], b2[j]);
        }
        __syncthreads();
    }

    // epilogue: bias + relu, vectorized stores
    float bv[8];
#pragma unroll
    for (int j = 0; j < 8; j++) bv[j] = bias[blockCol + tc * 8 + j];

#pragma unroll
    for (int i = 0; i < 4; i++) {
        float out0[8], out1[8];
#pragma unroll
        for (int j = 0; j < 8; j++) {
            float2 p = unpack2(acc[i][j]);
            out0[j] = fmaxf(p.x + bv[j], 0.0f);
            out1[j] = fmaxf(p.y + bv[j], 0.0f);
        }
        size_t r0 = blockRow + (size_t)tr * 8 + i * 2;
        float* c0 = C + r0 * N + blockCol + tc * 8;
        float* c1 = c0 + N;
        *reinterpret_cast<float4*>(c0)     = make_float4(out0[0], out0[1], out0[2], out0[3]);
        *reinterpret_cast<float4*>(c0 + 4) = make_float4(out0[4], out0[5], out0[6], out0[7]);
        *reinterpret_cast<float4*>(c1)     = make_float4(out1[0], out1[1], out1[2], out1[3]);
        *reinterpret_cast<float4*>(c1 + 4) = make_float4(out1[4], out1[5], out1[6], out1[7]);
    }
}

// ---------------- kernel 5: zero the tail (d2_loss scalar etc.) -------------
__global__ void zero_tail(float* out, size_t start, size_t count) {
    size_t i = (size_t)blockIdx.x * blockDim.x + threadIdx.x;
    if (i < count) out[start + i] = 0.0f;
}

// ---------------- launch ----------------------------------------------------
extern "C" void kernel_launch(void* const* d_in, const int* in_sizes, int n_in,
                              void* d_out, int out_size) {
    const float* x     = (const float*)d_in[0];
    const float* W_in  = (const float*)d_in[1];
    const float* b_in  = (const float*)d_in[2];
    const float* W_h   = (const float*)d_in[3];
    const float* b_h   = (const float*)d_in[4];
    const float* W_out = (const float*)d_in[5];
    const float* b_out = (const float*)d_in[6];
    float* out = (float*)d_out;

    float *h0, *h1;
    cudaGetSymbolAddress((void**)&h0, g_h0);
    cudaGetSymbolAddress((void**)&h1, g_h1);

    init_minmax<<<1, DIN>>>();
    colminmax<<<NROWS / 512, DIN>>>(x);
    discretize<<<NROWS / 512, DIN>>>(x);   // writes g_h0

    dim3 blk(256);
    dim3 g512(NROWS / BM, NH / BN);
    dim3 g128(NROWS / BM, DOUT / BN);

    gemm_bias_relu<<<g512, blk>>>(h0, W_in, b_in, h1, NH, DIN);   // l_in
    gemm_bias_relu<<<g512, blk>>>(h1, W_h,  b_h,  h0, NH, NH);    // l_h x5
    gemm_bias_relu<<<g512, blk>>>(h0, W_h,  b_h,  h1, NH, NH);
    gemm_bias_relu<<<g512, blk>>>(h1, W_h,  b_h,  h0, NH, NH);
    gemm_bias_relu<<<g512, blk>>>(h0, W_h,  b_h,  h1, NH, NH);
    gemm_bias_relu<<<g512, blk>>>(h1, W_h,  b_h,  h0, NH, NH);
    gemm_bias_relu<<<g128, blk>>>(h0, W_out, b_out, out, DOUT, NH);  // l_out

    size_t y_elems = (size_t)NROWS * DOUT;
    if ((size_t)out_size > y_elems) {
        size_t cnt = (size_t)out_size - y_elems;
        zero_tail<<<(unsigned)((cnt + 255) / 256), 256>>>(out, y_elems, cnt);
    }
}

// round 5
// speedup vs baseline: 1.5279x; 1.5279x over previous
#include <cuda_runtime.h>
#include <cuda_bf16.h>
#include <cstdint>

#define NROWS 131072
#define DIN   512
#define NH    512
#define DOUT  128
#define NBOUNDS 24

// ---------------- device scratch (plain row-major planes) -------------------
__device__ __align__(256) __nv_bfloat16 g_a0_hi[(size_t)NROWS * NH];
__device__ __align__(256) __nv_bfloat16 g_a0_lo[(size_t)NROWS * NH];
__device__ __align__(256) __nv_bfloat16 g_a1_hi[(size_t)NROWS * NH];
__device__ __align__(256) __nv_bfloat16 g_a1_lo[(size_t)NROWS * NH];
// weights transposed: [N][K]
__device__ __align__(256) __nv_bfloat16 g_win_hi[NH * DIN],  g_win_lo[NH * DIN];
__device__ __align__(256) __nv_bfloat16 g_wh_hi[NH * NH],    g_wh_lo[NH * NH];
__device__ __align__(256) __nv_bfloat16 g_wout_hi[DOUT * NH], g_wout_lo[DOUT * NH];
__device__ unsigned g_min_enc[DIN];
__device__ unsigned g_max_enc[DIN];

// ---------------- helpers ----------------------------------------------------
__device__ __forceinline__ uint32_t smem_u32(const void* p) {
    uint32_t a;
    asm("{ .reg .u64 t; cvta.to.shared.u64 t, %1; cvt.u32.u64 %0, t; }"
        : "=r"(a) : "l"(p));
    return a;
}
__device__ __forceinline__ void ldsm4(uint32_t* r, uint32_t a) {
    asm volatile("ldmatrix.sync.aligned.m8n8.x4.shared.b16 {%0,%1,%2,%3}, [%4];"
                 : "=r"(r[0]), "=r"(r[1]), "=r"(r[2]), "=r"(r[3]) : "r"(a));
}
__device__ __forceinline__ void mma16816(float* d, const uint32_t* a,
                                         uint32_t b0, uint32_t b1) {
    asm volatile(
        "mma.sync.aligned.m16n8k16.row.col.f32.bf16.bf16.f32 "
        "{%0,%1,%2,%3}, {%4,%5,%6,%7}, {%8,%9}, {%0,%1,%2,%3};"
        : "+f"(d[0]), "+f"(d[1]), "+f"(d[2]), "+f"(d[3])
        : "r"(a[0]), "r"(a[1]), "r"(a[2]), "r"(a[3]), "r"(b0), "r"(b1));
}
#define CP_ASYNC16(dst, src) \
    asm volatile("cp.async.cg.shared.global [%0], [%1], 16;" :: "r"(dst), "l"(src))
#define CP_COMMIT() asm volatile("cp.async.commit_group;" ::: "memory")
#define CP_WAIT1()  asm volatile("cp.async.wait_group 1;" ::: "memory")

__device__ __forceinline__ void split2(float a, float b, uint32_t& hi, uint32_t& lo) {
    __nv_bfloat16 ha = __float2bfloat16_rn(a), hb = __float2bfloat16_rn(b);
    __nv_bfloat16 la = __float2bfloat16_rn(a - __bfloat162float(ha));
    __nv_bfloat16 lb = __float2bfloat16_rn(b - __bfloat162float(hb));
    unsigned short uha = *reinterpret_cast<unsigned short*>(&ha);
    unsigned short uhb = *reinterpret_cast<unsigned short*>(&hb);
    unsigned short ula = *reinterpret_cast<unsigned short*>(&la);
    unsigned short ulb = *reinterpret_cast<unsigned short*>(&lb);
    hi = (uint32_t)uha | ((uint32_t)uhb << 16);
    lo = (uint32_t)ula | ((uint32_t)ulb << 16);
}

// ---------------- min/max + discretize ---------------------------------------
__device__ __forceinline__ unsigned enc_f(float f) {
    unsigned u = __float_as_uint(f);
    return (u & 0x80000000u) ? ~u : (u | 0x80000000u);
}
__device__ __forceinline__ float dec_f(unsigned e) {
    unsigned u = (e & 0x80000000u) ? (e & 0x7FFFFFFFu) : ~e;
    return __uint_as_float(u);
}
__global__ void init_minmax() {
    int i = threadIdx.x;
    g_min_enc[i] = 0xFFFFFFFFu;
    g_max_enc[i] = 0x00000000u;
}
__global__ void colminmax(const float* __restrict__ x) {
    const int col = threadIdx.x;
    const size_t base = (size_t)blockIdx.x * 512 * DIN + col;
    float v0 = x[base];
    float mn = v0, mx = v0;
    for (int r = 1; r < 512; r++) {
        float v = x[base + (size_t)r * DIN];
        mn = fminf(mn, v);
        mx = fmaxf(mx, v);
    }
    atomicMin(&g_min_enc[col], enc_f(mn));
    atomicMax(&g_max_enc[col], enc_f(mx));
}
__global__ void discretize(const float* __restrict__ x) {
    const int col = threadIdx.x;
    const float bmin = dec_f(g_min_enc[col]);
    const float bmax = dec_f(g_max_enc[col]);
    const float range = __fsub_rn(bmax, bmin);
    float bounds[NBOUNDS];
#pragma unroll
    for (int k = 0; k < NBOUNDS; k++) {
        float frac = __fdiv_rn((float)(k + 1), 25.0f);
        bounds[k] = __fadd_rn(bmin, __fmul_rn(range, frac));
    }
    const size_t base = (size_t)blockIdx.x * 512 * DIN + col;
    for (int r = 0; r < 512; r++) {
        float v = x[base + (size_t)r * DIN];
        int idx = 0;
#pragma unroll
        for (int k = 0; k < NBOUNDS; k++) idx += (bounds[k] < v) ? 1 : 0;
        g_a0_hi[base + (size_t)r * DIN] = __float2bfloat16_rn((float)idx);
    }
}

// ---------------- weight split + transpose ----------------------------------
__global__ void wprep(const float* __restrict__ W, __nv_bfloat16* __restrict__ hi,
                      __nv_bfloat16* __restrict__ lo, int N, int K) {
    int i = blockIdx.x * blockDim.x + threadIdx.x;
    if (i >= N * K) return;
    int k = i / N, n = i % N;  // W is [K][N]
    float w = W[i];
    __nv_bfloat16 h = __float2bfloat16_rn(w);
    __nv_bfloat16 l = __float2bfloat16_rn(w - __bfloat162float(h));
    hi[(size_t)n * K + k] = h;  // transposed [N][K]
    lo[(size_t)n * K + k] = l;
}

// ---------------- bf16 split-precision GEMM (mma.sync HMMA) -----------------
// C[M,N] = relu(A@W + bias); A planes [M][512], W planes transposed [N][512].
// Tiles: BM=128, BN=128, BK=64; 256 threads, warps 4(m) x 2(n), warp tile 32x64.
// SMEM per stage: Ah,Al,Bh,Bl 128x128B each (SW128 swizzled), 3 stages.
#define SM_STAGE 65536
#define SM_AH 0
#define SM_AL 16384
#define SM_BH 32768
#define SM_BL 49152

__global__ __launch_bounds__(256, 1)
void mlp_gemm(const __nv_bfloat16* __restrict__ Ahi, const __nv_bfloat16* __restrict__ Alo,
              const __nv_bfloat16* __restrict__ Bhi, const __nv_bfloat16* __restrict__ Blo,
              const float* __restrict__ bias,
              __nv_bfloat16* __restrict__ Ohi, __nv_bfloat16* __restrict__ Olo,
              float* __restrict__ Of32, int a_exact) {
    extern __shared__ __align__(1024) unsigned char sm[];
    const uint32_t smb = smem_u32(sm);
    const int tid = threadIdx.x;
    const int lane = tid & 31, wid = tid >> 5;
    const int wm = wid >> 1, wn = wid & 1;
    const int m0 = blockIdx.y * 128;
    const int n0 = blockIdx.x * 128;

    float acc[2][8][4];
#pragma unroll
    for (int i = 0; i < 2; i++)
#pragma unroll
        for (int j = 0; j < 8; j++)
#pragma unroll
            for (int q = 0; q < 4; q++) acc[i][j][q] = 0.0f;

    // ---- async tile loader: 128 rows x 64 cols bf16, SW128 swizzle ----
    auto loadp = [&](uint32_t sbase, const __nv_bfloat16* gp) {
#pragma unroll
        for (int it = 0; it < 4; it++) {
            int idx = tid + it * 256;
            int r = idx >> 3, c = idx & 7;
            uint32_t sa = sbase + r * 128 + ((c ^ (r & 7)) << 4);
            CP_ASYNC16(sa, gp + (size_t)r * 512 + c * 8);
        }
    };
    auto load_stage = [&](int stg, int ch) {
        uint32_t sb = smb + stg * SM_STAGE;
        int k0 = ch * 64;
        loadp(sb + SM_AH, Ahi + (size_t)m0 * 512 + k0);
        if (!a_exact) loadp(sb + SM_AL, Alo + (size_t)m0 * 512 + k0);
        loadp(sb + SM_BH, Bhi + (size_t)n0 * 512 + k0);
        loadp(sb + SM_BL, Blo + (size_t)n0 * 512 + k0);
    };

    const int arow = lane & 15;
    const int kbl  = lane >> 4;
    const int npairs = a_exact ? 2 : 3;

    load_stage(0, 0); CP_COMMIT();
    load_stage(1, 1); CP_COMMIT();

#pragma unroll 1
    for (int ch = 0; ch < 8; ch++) {
        CP_WAIT1();
        __syncthreads();
        if (ch + 2 < 8) load_stage((ch + 2) % 3, ch + 2);
        CP_COMMIT();

        const uint32_t sb = smb + (ch % 3) * SM_STAGE;
#pragma unroll 1
        for (int p = 0; p < npairs; p++) {
            const uint32_t ab = sb + (p == 2 ? SM_AL : SM_AH);
            const uint32_t bb = sb + (p == 1 ? SM_BL : SM_BH);
#pragma unroll
            for (int kk = 0; kk < 4; kk++) {
                uint32_t a[2][4];
#pragma unroll
                for (int mf = 0; mf < 2; mf++) {
                    int r = wm * 32 + mf * 16 + arow;
                    int c = kk * 2 + kbl;
                    ldsm4(a[mf], ab + r * 128 + ((c ^ (r & 7)) << 4));
                }
#pragma unroll
                for (int g = 0; g < 4; g++) {
                    uint32_t b[4];
                    int r = wn * 64 + g * 16 + arow;
                    int c = kk * 2 + kbl;
                    ldsm4(b, bb + r * 128 + ((c ^ (r & 7)) << 4));
#pragma unroll
                    for (int mf = 0; mf < 2; mf++) {
                        mma16816(acc[mf][2 * g],     a[mf], b[0], b[2]);
                        mma16816(acc[mf][2 * g + 1], a[mf], b[1], b[3]);
                    }
                }
            }
        }
    }

    // ---- epilogue: bias + relu, split bf16 (hidden) or fp32 (final) ----
    const int qr = lane >> 2, qc = lane & 3;
#pragma unroll
    for (int mf = 0; mf < 2; mf++) {
#pragma unroll
        for (int nf = 0; nf < 8; nf++) {
            int n = n0 + wn * 64 + nf * 8 + qc * 2;
            float bv0 = bias[n], bv1 = bias[n + 1];
            int r0 = m0 + wm * 32 + mf * 16 + qr;
            float v00 = fmaxf(acc[mf][nf][0] + bv0, 0.0f);
            float v01 = fmaxf(acc[mf][nf][1] + bv1, 0.0f);
            float v10 = fmaxf(acc[mf][nf][2] + bv0, 0.0f);
            float v11 = fmaxf(acc[mf][nf][3] + bv1, 0.0f);
            if (Of32) {
                *reinterpret_cast<float2*>(Of32 + (size_t)r0 * DOUT + n) =
                    make_float2(v00, v01);
                *reinterpret_cast<float2*>(Of32 + (size_t)(r0 + 8) * DOUT + n) =
                    make_float2(v10, v11);
            } else {
                uint32_t h0, l0, h1, l1;
                split2(v00, v01, h0, l0);
                split2(v10, v11, h1, l1);
                *reinterpret_cast<uint32_t*>(Ohi + (size_t)r0 * NH + n) = h0;
                *reinterpret_cast<uint32_t*>(Olo + (size_t)r0 * NH + n) = l0;
                *reinterpret_cast<uint32_t*>(Ohi + (size_t)(r0 + 8) * NH + n) = h1;
                *reinterpret_cast<uint32_t*>(Olo + (size_t)(r0 + 8) * NH + n) = l1;
            }
        }
    }
}

// ---------------- tail zero --------------------------------------------------
__global__ void zero_tail(float* out, size_t start, size_t count) {
    size_t i = (size_t)blockIdx.x * blockDim.x + threadIdx.x;
    if (i < count) out[start + i] = 0.0f;
}

// ---------------- launch -----------------------------------------------------
extern "C" void kernel_launch(void* const* d_in, const int* in_sizes, int n_in,
                              void* d_out, int out_size) {
    const float* x     = (const float*)d_in[0];
    const float* W_in  = (const float*)d_in[1];
    const float* b_in  = (const float*)d_in[2];
    const float* W_h   = (const float*)d_in[3];
    const float* b_h   = (const float*)d_in[4];
    const float* W_out = (const float*)d_in[5];
    const float* b_out = (const float*)d_in[6];
    float* out = (float*)d_out;

    __nv_bfloat16 *a0h, *a0l, *a1h, *a1l, *wih, *wil, *whh, *whl, *woh, *wol;
    cudaGetSymbolAddress((void**)&a0h, g_a0_hi);
    cudaGetSymbolAddress((void**)&a0l, g_a0_lo);
    cudaGetSymbolAddress((void**)&a1h, g_a1_hi);
    cudaGetSymbolAddress((void**)&a1l, g_a1_lo);
    cudaGetSymbolAddress((void**)&wih, g_win_hi);
    cudaGetSymbolAddress((void**)&wil, g_win_lo);
    cudaGetSymbolAddress((void**)&whh, g_wh_hi);
    cudaGetSymbolAddress((void**)&whl, g_wh_lo);
    cudaGetSymbolAddress((void**)&woh, g_wout_hi);
    cudaGetSymbolAddress((void**)&wol, g_wout_lo);

    cudaFuncSetAttribute(mlp_gemm, cudaFuncAttributeMaxDynamicSharedMemorySize,
                         3 * SM_STAGE);

    init_minmax<<<1, DIN>>>();
    colminmax<<<NROWS / 512, DIN>>>(x);
    discretize<<<NROWS / 512, DIN>>>(x);

    wprep<<<(DIN * NH + 255) / 256, 256>>>(W_in, wih, wil, NH, DIN);
    wprep<<<(NH * NH + 255) / 256, 256>>>(W_h, whh, whl, NH, NH);
    wprep<<<(NH * DOUT + 255) / 256, 256>>>(W_out, woh, wol, DOUT, NH);

    dim3 blk(256);
    dim3 gh(4, NROWS / 128);   // hidden: N=512 -> 4 n-tiles
    dim3 gf(1, NROWS / 128);   // final:  N=128 -> 1 n-tile
    const size_t smem = 3 * SM_STAGE;

    // L1: A exact (ints), 2 terms
    mlp_gemm<<<gh, blk, smem>>>(a0h, nullptr, wih, wil, b_in, a1h, a1l, nullptr, 1);
    // L2..L6: shared W_h, ping-pong, 3 terms
    mlp_gemm<<<gh, blk, smem>>>(a1h, a1l, whh, whl, b_h, a0h, a0l, nullptr, 0);
    mlp_gemm<<<gh, blk, smem>>>(a0h, a0l, whh, whl, b_h, a1h, a1l, nullptr, 0);
    mlp_gemm<<<gh, blk, smem>>>(a1h, a1l, whh, whl, b_h, a0h, a0l, nullptr, 0);
    mlp_gemm<<<gh, blk, smem>>>(a0h, a0l, whh, whl, b_h, a1h, a1l, nullptr, 0);
    mlp_gemm<<<gh, blk, smem>>>(a1h, a1l, whh, whl, b_h, a0h, a0l, nullptr, 0);
    // L7: final, fp32 out
    mlp_gemm<<<gf, blk, smem>>>(a0h, a0l, woh, wol, b_out, nullptr, nullptr, out, 0);

    size_t y_elems = (size_t)NROWS * DOUT;
    if ((size_t)out_size > y_elems) {
        size_t cnt = (size_t)out_size - y_elems;
        zero_tail<<<(unsigned)((cnt + 255) / 256), 256>>>(out, y_elems, cnt);
    }
}

// round 7
// speedup vs baseline: 2.3246x; 1.5214x over previous
#include <cuda_runtime.h>
#include <cuda_bf16.h>
#include <cstdint>

#define NROWS 131072
#define DIN   512
#define NH    512
#define DOUT  128
#define NBOUNDS 24

// ---------------- device scratch (plain row-major planes) -------------------
__device__ __align__(256) __nv_bfloat16 g_a0_hi[(size_t)NROWS * NH];
__device__ __align__(256) __nv_bfloat16 g_a0_lo[(size_t)NROWS * NH];
__device__ __align__(256) __nv_bfloat16 g_a1_hi[(size_t)NROWS * NH];
__device__ __align__(256) __nv_bfloat16 g_a1_lo[(size_t)NROWS * NH];
// weights transposed: [N][K]
__device__ __align__(256) __nv_bfloat16 g_win_hi[NH * DIN],  g_win_lo[NH * DIN];
__device__ __align__(256) __nv_bfloat16 g_wh_hi[NH * NH],    g_wh_lo[NH * NH];
__device__ __align__(256) __nv_bfloat16 g_wout_hi[DOUT * NH], g_wout_lo[DOUT * NH];
__device__ unsigned g_min_enc[DIN];
__device__ unsigned g_max_enc[DIN];

// ---------------- helpers ----------------------------------------------------
__device__ __forceinline__ uint32_t smem_u32(const void* p) {
    uint32_t a;
    asm("{ .reg .u64 t; cvta.to.shared.u64 t, %1; cvt.u32.u64 %0, t; }"
        : "=r"(a) : "l"(p));
    return a;
}
__device__ __forceinline__ void ldsm4(uint32_t* r, uint32_t a) {
    asm volatile("ldmatrix.sync.aligned.m8n8.x4.shared.b16 {%0,%1,%2,%3}, [%4];"
                 : "=r"(r[0]), "=r"(r[1]), "=r"(r[2]), "=r"(r[3]) : "r"(a));
}
__device__ __forceinline__ void mma16816(float* d, const uint32_t* a,
                                         uint32_t b0, uint32_t b1) {
    asm volatile(
        "mma.sync.aligned.m16n8k16.row.col.f32.bf16.bf16.f32 "
        "{%0,%1,%2,%3}, {%4,%5,%6,%7}, {%8,%9}, {%0,%1,%2,%3};"
        : "+f"(d[0]), "+f"(d[1]), "+f"(d[2]), "+f"(d[3])
        : "r"(a[0]), "r"(a[1]), "r"(a[2]), "r"(a[3]), "r"(b0), "r"(b1));
}
#define CP_ASYNC16(dst, src) \
    asm volatile("cp.async.cg.shared.global [%0], [%1], 16;" :: "r"(dst), "l"(src))
#define CP_COMMIT() asm volatile("cp.async.commit_group;" ::: "memory")
#define CP_WAIT1()  asm volatile("cp.async.wait_group 1;" ::: "memory")

__device__ __forceinline__ void split2(float a, float b, uint32_t& hi, uint32_t& lo) {
    __nv_bfloat16 ha = __float2bfloat16_rn(a), hb = __float2bfloat16_rn(b);
    __nv_bfloat16 la = __float2bfloat16_rn(a - __bfloat162float(ha));
    __nv_bfloat16 lb = __float2bfloat16_rn(b - __bfloat162float(hb));
    unsigned short uha = *reinterpret_cast<unsigned short*>(&ha);
    unsigned short uhb = *reinterpret_cast<unsigned short*>(&hb);
    unsigned short ula = *reinterpret_cast<unsigned short*>(&la);
    unsigned short ulb = *reinterpret_cast<unsigned short*>(&lb);
    hi = (uint32_t)uha | ((uint32_t)uhb << 16);
    lo = (uint32_t)ula | ((uint32_t)ulb << 16);
}

// ---------------- min/max + discretize ---------------------------------------
__device__ __forceinline__ unsigned enc_f(float f) {
    unsigned u = __float_as_uint(f);
    return (u & 0x80000000u) ? ~u : (u | 0x80000000u);
}
__device__ __forceinline__ float dec_f(unsigned e) {
    unsigned u = (e & 0x80000000u) ? (e & 0x7FFFFFFFu) : ~e;
    return __uint_as_float(u);
}
__global__ void init_minmax() {
    int i = threadIdx.x;
    g_min_enc[i] = 0xFFFFFFFFu;
    g_max_enc[i] = 0x00000000u;
}
__global__ void colminmax(const float* __restrict__ x) {
    const int col = threadIdx.x;
    const size_t base = (size_t)blockIdx.x * 512 * DIN + col;
    float v0 = x[base];
    float mn = v0, mx = v0;
    for (int r = 1; r < 512; r++) {
        float v = x[base + (size_t)r * DIN];
        mn = fminf(mn, v);
        mx = fmaxf(mx, v);
    }
    atomicMin(&g_min_enc[col], enc_f(mn));
    atomicMax(&g_max_enc[col], enc_f(mx));
}
__global__ void discretize(const float* __restrict__ x) {
    const int col = threadIdx.x;
    const float bmin = dec_f(g_min_enc[col]);
    const float bmax = dec_f(g_max_enc[col]);
    const float range = __fsub_rn(bmax, bmin);
    float bounds[NBOUNDS];
#pragma unroll
    for (int k = 0; k < NBOUNDS; k++) {
        float frac = __fdiv_rn((float)(k + 1), 25.0f);
        bounds[k] = __fadd_rn(bmin, __fmul_rn(range, frac));
    }
    const size_t base = (size_t)blockIdx.x * 512 * DIN + col;
    for (int r = 0; r < 512; r++) {
        float v = x[base + (size_t)r * DIN];
        int idx = 0;
#pragma unroll
        for (int k = 0; k < NBOUNDS; k++) idx += (bounds[k] < v) ? 1 : 0;
        g_a0_hi[base + (size_t)r * DIN] = __float2bfloat16_rn((float)idx);
    }
}

// ---------------- weight split + transpose ----------------------------------
__global__ void wprep(const float* __restrict__ W, __nv_bfloat16* __restrict__ hi,
                      __nv_bfloat16* __restrict__ lo, int N, int K) {
    int i = blockIdx.x * blockDim.x + threadIdx.x;
    if (i >= N * K) return;
    int k = i / N, n = i % N;  // W is [K][N]
    float w = W[i];
    __nv_bfloat16 h = __float2bfloat16_rn(w);
    __nv_bfloat16 l = __float2bfloat16_rn(w - __bfloat162float(h));
    hi[(size_t)n * K + k] = h;  // transposed [N][K]
    lo[(size_t)n * K + k] = l;
}

// ---------------- bf16 split-precision GEMM (mma.sync HMMA) -----------------
// C[M,N] = relu(A@W + bias); A planes [M][512], W planes transposed [N][512].
// Tiles: BM=128, BN=128, BK=64; 512 threads, warps 4(m) x 4(n), warp tile 32x32.
// SMEM per stage: Ah,Al,Bh,Bl 128x128B each (SW128 swizzled), 3 stages.
#define SM_STAGE 65536
#define SM_AH 0
#define SM_AL 16384
#define SM_BH 32768
#define SM_BL 49152

__global__ __launch_bounds__(512, 1)
void mlp_gemm(const __nv_bfloat16* __restrict__ Ahi, const __nv_bfloat16* __restrict__ Alo,
              const __nv_bfloat16* __restrict__ Bhi, const __nv_bfloat16* __restrict__ Blo,
              const float* __restrict__ bias,
              __nv_bfloat16* __restrict__ Ohi, __nv_bfloat16* __restrict__ Olo,
              float* __restrict__ Of32, int a_exact) {
    extern __shared__ __align__(1024) unsigned char sm[];
    const uint32_t smb = smem_u32(sm);
    const int tid = threadIdx.x;
    const int lane = tid & 31, wid = tid >> 5;
    const int wm = wid >> 2, wn = wid & 3;      // 4 x 4 warp grid
    const int m0 = blockIdx.y * 128;
    const int n0 = blockIdx.x * 128;

    float acc[2][4][4];                         // mf(16 rows) x nf(8 cols) x quad
#pragma unroll
    for (int i = 0; i < 2; i++)
#pragma unroll
        for (int j = 0; j < 4; j++)
#pragma unroll
            for (int q = 0; q < 4; q++) acc[i][j][q] = 0.0f;

    // ---- async tile loader: 128 rows x 64 cols bf16, SW128 swizzle ----
    auto loadp = [&](uint32_t sbase, const __nv_bfloat16* gp) {
#pragma unroll
        for (int it = 0; it < 2; it++) {
            int idx = tid + it * 512;
            int r = idx >> 3, c = idx & 7;
            uint32_t sa = sbase + r * 128 + ((c ^ (r & 7)) << 4);
            CP_ASYNC16(sa, gp + (size_t)r * 512 + c * 8);
        }
    };
    auto load_stage = [&](int stg, int ch) {
        uint32_t sb = smb + stg * SM_STAGE;
        int k0 = ch * 64;
        loadp(sb + SM_AH, Ahi + (size_t)m0 * 512 + k0);
        if (!a_exact) loadp(sb + SM_AL, Alo + (size_t)m0 * 512 + k0);
        loadp(sb + SM_BH, Bhi + (size_t)n0 * 512 + k0);
        loadp(sb + SM_BL, Blo + (size_t)n0 * 512 + k0);
    };

    const int arow = lane & 15;   // row within 16-row fragment
    const int kbl  = lane >> 4;   // k-half selector
    const int npairs = a_exact ? 2 : 3;

    load_stage(0, 0); CP_COMMIT();
    load_stage(1, 1); CP_COMMIT();

#pragma unroll 1
    for (int ch = 0; ch < 8; ch++) {
        CP_WAIT1();
        __syncthreads();
        if (ch + 2 < 8) load_stage((ch + 2) % 3, ch + 2);
        CP_COMMIT();

        const uint32_t sb = smb + (ch % 3) * SM_STAGE;
#pragma unroll 1
        for (int p = 0; p < npairs; p++) {
            const uint32_t ab = sb + (p == 2 ? SM_AL : SM_AH);
            const uint32_t bb = sb + (p == 1 ? SM_BL : SM_BH);
#pragma unroll
            for (int kk = 0; kk < 4; kk++) {
                const int c = kk * 2 + kbl;
                // load all fragments for this k-slice first
                uint32_t a[2][4], b[2][4];
#pragma unroll
                for (int mf = 0; mf < 2; mf++) {
                    int r = wm * 32 + mf * 16 + arow;
                    ldsm4(a[mf], ab + r * 128 + ((c ^ (r & 7)) << 4));
                }
#pragma unroll
                for (int g = 0; g < 2; g++) {
                    int r = wn * 32 + g * 16 + arow;
                    ldsm4(b[g], bb + r * 128 + ((c ^ (r & 7)) << 4));
                }
                // 8 mmas, no pending loads
#pragma unroll
                for (int g = 0; g < 2; g++)
#pragma unroll
                    for (int mf = 0; mf < 2; mf++) {
                        mma16816(acc[mf][2 * g],     a[mf], b[g][0], b[g][2]);
                        mma16816(acc[mf][2 * g + 1], a[mf], b[g][1], b[g][3]);
                    }
            }
        }
    }

    // ---- epilogue: bias + relu, split bf16 (hidden) or fp32 (final) ----
    const int qr = lane >> 2, qc = lane & 3;
#pragma unroll
    for (int mf = 0; mf < 2; mf++) {
#pragma unroll
        for (int nf = 0; nf < 4; nf++) {
            int n = n0 + wn * 32 + nf * 8 + qc * 2;
            float bv0 = bias[n], bv1 = bias[n + 1];
            int r0 = m0 + wm * 32 + mf * 16 + qr;
            float v00 = fmaxf(acc[mf][nf][0] + bv0, 0.0f);
            float v01 = fmaxf(acc[mf][nf][1] + bv1, 0.0f);
            float v10 = fmaxf(acc[mf][nf][2] + bv0, 0.0f);
            float v11 = fmaxf(acc[mf][nf][3] + bv1, 0.0f);
            if (Of32) {
                *reinterpret_cast<float2*>(Of32 + (size_t)r0 * DOUT + n) =
                    make_float2(v00, v01);
                *reinterpret_cast<float2*>(Of32 + (size_t)(r0 + 8) * DOUT + n) =
                    make_float2(v10, v11);
            } else {
                uint32_t h0, l0, h1, l1;
                split2(v00, v01, h0, l0);
                split2(v10, v11, h1, l1);
                *reinterpret_cast<uint32_t*>(Ohi + (size_t)r0 * NH + n) = h0;
                *reinterpret_cast<uint32_t*>(Olo + (size_t)r0 * NH + n) = l0;
                *reinterpret_cast<uint32_t*>(Ohi + (size_t)(r0 + 8) * NH + n) = h1;
                *reinterpret_cast<uint32_t*>(Olo + (size_t)(r0 + 8) * NH + n) = l1;
            }
        }
    }
}

// ---------------- tail zero --------------------------------------------------
__global__ void zero_tail(float* out, size_t start, size_t count) {
    size_t i = (size_t)blockIdx.x * blockDim.x + threadIdx.x;
    if (i < count) out[start + i] = 0.0f;
}

// ---------------- launch -----------------------------------------------------
extern "C" void kernel_launch(void* const* d_in, const int* in_sizes, int n_in,
                              void* d_out, int out_size) {
    const float* x     = (const float*)d_in[0];
    const float* W_in  = (const float*)d_in[1];
    const float* b_in  = (const float*)d_in[2];
    const float* W_h   = (const float*)d_in[3];
    const float* b_h   = (const float*)d_in[4];
    const float* W_out = (const float*)d_in[5];
    const float* b_out = (const float*)d_in[6];
    float* out = (float*)d_out;

    __nv_bfloat16 *a0h, *a0l, *a1h, *a1l, *wih, *wil, *whh, *whl, *woh, *wol;
    cudaGetSymbolAddress((void**)&a0h, g_a0_hi);
    cudaGetSymbolAddress((void**)&a0l, g_a0_lo);
    cudaGetSymbolAddress((void**)&a1h, g_a1_hi);
    cudaGetSymbolAddress((void**)&a1l, g_a1_lo);
    cudaGetSymbolAddress((void**)&wih, g_win_hi);
    cudaGetSymbolAddress((void**)&wil, g_win_lo);
    cudaGetSymbolAddress((void**)&whh, g_wh_hi);
    cudaGetSymbolAddress((void**)&whl, g_wh_lo);
    cudaGetSymbolAddress((void**)&woh, g_wout_hi);
    cudaGetSymbolAddress((void**)&wol, g_wout_lo);

    cudaFuncSetAttribute(mlp_gemm, cudaFuncAttributeMaxDynamicSharedMemorySize,
                         3 * SM_STAGE);

    init_minmax<<<1, DIN>>>();
    colminmax<<<NROWS / 512, DIN>>>(x);
    discretize<<<NROWS / 512, DIN>>>(x);

    wprep<<<(DIN * NH + 255) / 256, 256>>>(W_in, wih, wil, NH, DIN);
    wprep<<<(NH * NH + 255) / 256, 256>>>(W_h, whh, whl, NH, NH);
    wprep<<<(NH * DOUT + 255) / 256, 256>>>(W_out, woh, wol, DOUT, NH);

    dim3 blk(512);
    dim3 gh(4, NROWS / 128);   // hidden: N=512 -> 4 n-tiles
    dim3 gf(1, NROWS / 128);   // final:  N=128 -> 1 n-tile
    const size_t smem = 3 * SM_STAGE;

    // L1: A exact (ints), 2 terms
    mlp_gemm<<<gh, blk, smem>>>(a0h, nullptr, wih, wil, b_in, a1h, a1l, nullptr, 1);
    // L2..L6: shared W_h, ping-pong, 3 terms
    mlp_gemm<<<gh, blk, smem>>>(a1h, a1l, whh, whl, b_h, a0h, a0l, nullptr, 0);
    mlp_gemm<<<gh, blk, smem>>>(a0h, a0l, whh, whl, b_h, a1h, a1l, nullptr, 0);
    mlp_gemm<<<gh, blk, smem>>>(a1h, a1l, whh, whl, b_h, a0h, a0l, nullptr, 0);
    mlp_gemm<<<gh, blk, smem>>>(a0h, a0l, whh, whl, b_h, a1h, a1l, nullptr, 0);
    mlp_gemm<<<gh, blk, smem>>>(a1h, a1l, whh, whl, b_h, a0h, a0l, nullptr, 0);
    // L7: final, fp32 out
    mlp_gemm<<<gf, blk, smem>>>(a0h, a0l, woh, wol, b_out, nullptr, nullptr, out, 0);

    size_t y_elems = (size_t)NROWS * DOUT;
    if ((size_t)out_size > y_elems) {
        size_t cnt = (size_t)out_size - y_elems;
        zero_tail<<<(unsigned)((cnt + 255) / 256), 256>>>(out, y_elems, cnt);
    }
}

// round 8
// speedup vs baseline: 2.3564x; 1.0137x over previous
#include <cuda_runtime.h>
#include <cuda_bf16.h>
#include <cstdint>

#define NROWS 131072
#define DIN   512
#define NH    512
#define DOUT  128
#define NBOUNDS 24

// ---------------- device scratch (plain row-major planes) -------------------
__device__ __align__(256) __nv_bfloat16 g_a0_hi[(size_t)NROWS * NH];
__device__ __align__(256) __nv_bfloat16 g_a0_lo[(size_t)NROWS * NH];
__device__ __align__(256) __nv_bfloat16 g_a1_hi[(size_t)NROWS * NH];
__device__ __align__(256) __nv_bfloat16 g_a1_lo[(size_t)NROWS * NH];
// weights transposed: [N][K]
__device__ __align__(256) __nv_bfloat16 g_win_hi[NH * DIN],  g_win_lo[NH * DIN];
__device__ __align__(256) __nv_bfloat16 g_wh_hi[NH * NH],    g_wh_lo[NH * NH];
__device__ __align__(256) __nv_bfloat16 g_wout_hi[DOUT * NH], g_wout_lo[DOUT * NH];
__device__ unsigned g_min_enc[DIN];
__device__ unsigned g_max_enc[DIN];

// ---------------- helpers ----------------------------------------------------
__device__ __forceinline__ uint32_t smem_u32(const void* p) {
    uint32_t a;
    asm("{ .reg .u64 t; cvta.to.shared.u64 t, %1; cvt.u32.u64 %0, t; }"
        : "=r"(a) : "l"(p));
    return a;
}
__device__ __forceinline__ void ldsm4(uint32_t* r, uint32_t a) {
    asm volatile("ldmatrix.sync.aligned.m8n8.x4.shared.b16 {%0,%1,%2,%3}, [%4];"
                 : "=r"(r[0]), "=r"(r[1]), "=r"(r[2]), "=r"(r[3]) : "r"(a));
}
__device__ __forceinline__ void mma16816(float* d, const uint32_t* a,
                                         uint32_t b0, uint32_t b1) {
    asm volatile(
        "mma.sync.aligned.m16n8k16.row.col.f32.bf16.bf16.f32 "
        "{%0,%1,%2,%3}, {%4,%5,%6,%7}, {%8,%9}, {%0,%1,%2,%3};"
        : "+f"(d[0]), "+f"(d[1]), "+f"(d[2]), "+f"(d[3])
        : "r"(a[0]), "r"(a[1]), "r"(a[2]), "r"(a[3]), "r"(b0), "r"(b1));
}
#define CP_ASYNC16(dst, src) \
    asm volatile("cp.async.cg.shared.global [%0], [%1], 16;" :: "r"(dst), "l"(src))
#define CP_COMMIT() asm volatile("cp.async.commit_group;" ::: "memory")
#define CP_WAIT1()  asm volatile("cp.async.wait_group 1;" ::: "memory")

__device__ __forceinline__ void split2(float a, float b, uint32_t& hi, uint32_t& lo) {
    __nv_bfloat16 ha = __float2bfloat16_rn(a), hb = __float2bfloat16_rn(b);
    __nv_bfloat16 la = __float2bfloat16_rn(a - __bfloat162float(ha));
    __nv_bfloat16 lb = __float2bfloat16_rn(b - __bfloat162float(hb));
    unsigned short uha = *reinterpret_cast<unsigned short*>(&ha);
    unsigned short uhb = *reinterpret_cast<unsigned short*>(&hb);
    unsigned short ula = *reinterpret_cast<unsigned short*>(&la);
    unsigned short ulb = *reinterpret_cast<unsigned short*>(&lb);
    hi = (uint32_t)uha | ((uint32_t)uhb << 16);
    lo = (uint32_t)ula | ((uint32_t)ulb << 16);
}

// ---------------- min/max + discretize ---------------------------------------
__device__ __forceinline__ unsigned enc_f(float f) {
    unsigned u = __float_as_uint(f);
    return (u & 0x80000000u) ? ~u : (u | 0x80000000u);
}
__device__ __forceinline__ float dec_f(unsigned e) {
    unsigned u = (e & 0x80000000u) ? (e & 0x7FFFFFFFu) : ~e;
    return __uint_as_float(u);
}
__global__ void init_minmax() {
    int i = threadIdx.x;
    g_min_enc[i] = 0xFFFFFFFFu;
    g_max_enc[i] = 0x00000000u;
}
__global__ void colminmax(const float* __restrict__ x) {
    const int col = threadIdx.x;
    const size_t base = (size_t)blockIdx.x * 512 * DIN + col;
    float v0 = x[base];
    float mn = v0, mx = v0;
    for (int r = 1; r < 512; r++) {
        float v = x[base + (size_t)r * DIN];
        mn = fminf(mn, v);
        mx = fmaxf(mx, v);
    }
    atomicMin(&g_min_enc[col], enc_f(mn));
    atomicMax(&g_max_enc[col], enc_f(mx));
}
__global__ void discretize(const float* __restrict__ x) {
    const int col = threadIdx.x;
    const float bmin = dec_f(g_min_enc[col]);
    const float bmax = dec_f(g_max_enc[col]);
    const float range = __fsub_rn(bmax, bmin);
    float bounds[NBOUNDS];
#pragma unroll
    for (int k = 0; k < NBOUNDS; k++) {
        float frac = __fdiv_rn((float)(k + 1), 25.0f);
        bounds[k] = __fadd_rn(bmin, __fmul_rn(range, frac));
    }
    const size_t base = (size_t)blockIdx.x * 512 * DIN + col;
    for (int r = 0; r < 512; r++) {
        float v = x[base + (size_t)r * DIN];
        int idx = 0;
#pragma unroll
        for (int k = 0; k < NBOUNDS; k++) idx += (bounds[k] < v) ? 1 : 0;
        g_a0_hi[base + (size_t)r * DIN] = __float2bfloat16_rn((float)idx);
    }
}

// ---------------- weight split + transpose ----------------------------------
__global__ void wprep(const float* __restrict__ W, __nv_bfloat16* __restrict__ hi,
                      __nv_bfloat16* __restrict__ lo, int N, int K) {
    int i = blockIdx.x * blockDim.x + threadIdx.x;
    if (i >= N * K) return;
    int k = i / N, n = i % N;  // W is [K][N]
    float w = W[i];
    __nv_bfloat16 h = __float2bfloat16_rn(w);
    __nv_bfloat16 l = __float2bfloat16_rn(w - __bfloat162float(h));
    hi[(size_t)n * K + k] = h;  // transposed [N][K]
    lo[(size_t)n * K + k] = l;
}

// ---------------- bf16 split-precision GEMM (mma.sync HMMA) -----------------
// C[M,N] = relu(A@W + bias); A planes [M][512], W planes transposed [N][512].
// Tiles: BM=128, BN=128, BK=64; 512 threads, warps 4(m) x 4(n), warp tile 32x32.
// Inner loop: load all plane fragments ONCE per k-slice (8 ldsm4), then 24 mmas.
#define SM_STAGE 65536
#define SM_AH 0
#define SM_AL 16384
#define SM_BH 32768
#define SM_BL 49152

template <int AEXACT, int FINAL>
__global__ __launch_bounds__(512, 1)
void mlp_gemm(const __nv_bfloat16* __restrict__ Ahi, const __nv_bfloat16* __restrict__ Alo,
              const __nv_bfloat16* __restrict__ Bhi, const __nv_bfloat16* __restrict__ Blo,
              const float* __restrict__ bias,
              __nv_bfloat16* __restrict__ Ohi, __nv_bfloat16* __restrict__ Olo,
              float* __restrict__ Of32) {
    extern __shared__ __align__(1024) unsigned char sm[];
    const uint32_t smb = smem_u32(sm);
    const int tid = threadIdx.x;
    const int lane = tid & 31, wid = tid >> 5;
    const int wm = wid >> 2, wn = wid & 3;      // 4 x 4 warp grid
    const int m0 = blockIdx.y * 128;
    const int n0 = blockIdx.x * 128;

    float acc[2][4][4];                         // mf(16 rows) x nf(8 cols) x quad
#pragma unroll
    for (int i = 0; i < 2; i++)
#pragma unroll
        for (int j = 0; j < 4; j++)
#pragma unroll
            for (int q = 0; q < 4; q++) acc[i][j][q] = 0.0f;

    // ---- async tile loader: 128 rows x 64 cols bf16, SW128 swizzle ----
    auto loadp = [&](uint32_t sbase, const __nv_bfloat16* gp) {
#pragma unroll
        for (int it = 0; it < 2; it++) {
            int idx = tid + it * 512;
            int r = idx >> 3, c = idx & 7;
            uint32_t sa = sbase + r * 128 + ((c ^ (r & 7)) << 4);
            CP_ASYNC16(sa, gp + (size_t)r * 512 + c * 8);
        }
    };
    auto load_stage = [&](int stg, int ch) {
        uint32_t sb = smb + stg * SM_STAGE;
        int k0 = ch * 64;
        loadp(sb + SM_AH, Ahi + (size_t)m0 * 512 + k0);
        if (!AEXACT) loadp(sb + SM_AL, Alo + (size_t)m0 * 512 + k0);
        loadp(sb + SM_BH, Bhi + (size_t)n0 * 512 + k0);
        loadp(sb + SM_BL, Blo + (size_t)n0 * 512 + k0);
    };

    const int arow = lane & 15;   // row within 16-row fragment
    const int kbl  = lane >> 4;   // k-half selector

    // precomputed per-fragment row offsets
    uint32_t aoff[2], boff[2];
    int amod[2], bmod[2];
#pragma unroll
    for (int mf = 0; mf < 2; mf++) {
        int r = wm * 32 + mf * 16 + arow;
        aoff[mf] = r * 128; amod[mf] = r & 7;
    }
#pragma unroll
    for (int g = 0; g < 2; g++) {
        int r = wn * 32 + g * 16 + arow;
        boff[g] = r * 128; bmod[g] = r & 7;
    }

    load_stage(0, 0); CP_COMMIT();
    load_stage(1, 1); CP_COMMIT();

#pragma unroll 1
    for (int ch = 0; ch < 8; ch++) {
        CP_WAIT1();
        __syncthreads();
        if (ch + 2 < 8) load_stage((ch + 2) % 3, ch + 2);
        CP_COMMIT();

        const uint32_t sb = smb + (ch % 3) * SM_STAGE;
#pragma unroll
        for (int kk = 0; kk < 4; kk++) {
            const int c = kk * 2 + kbl;
            uint32_t ah[2][4], al[2][4], bh[2][4], bl[2][4];
#pragma unroll
            for (int mf = 0; mf < 2; mf++) {
                uint32_t o = aoff[mf] + ((c ^ amod[mf]) << 4);
                ldsm4(ah[mf], sb + SM_AH + o);
                if (!AEXACT) ldsm4(al[mf], sb + SM_AL + o);
            }
#pragma unroll
            for (int g = 0; g < 2; g++) {
                uint32_t o = boff[g] + ((c ^ bmod[g]) << 4);
                ldsm4(bh[g], sb + SM_BH + o);
                ldsm4(bl[g], sb + SM_BL + o);
            }
#pragma unroll
            for (int g = 0; g < 2; g++)
#pragma unroll
                for (int mf = 0; mf < 2; mf++) {
                    mma16816(acc[mf][2 * g],     ah[mf], bh[g][0], bh[g][2]);
                    mma16816(acc[mf][2 * g + 1], ah[mf], bh[g][1], bh[g][3]);
                    mma16816(acc[mf][2 * g],     ah[mf], bl[g][0], bl[g][2]);
                    mma16816(acc[mf][2 * g + 1], ah[mf], bl[g][1], bl[g][3]);
                    if (!AEXACT) {
                        mma16816(acc[mf][2 * g],     al[mf], bh[g][0], bh[g][2]);
                        mma16816(acc[mf][2 * g + 1], al[mf], bh[g][1], bh[g][3]);
                    }
                }
        }
    }

    // ---- epilogue: bias + relu, split bf16 (hidden) or fp32 (final) ----
    const int qr = lane >> 2, qc = lane & 3;
#pragma unroll
    for (int mf = 0; mf < 2; mf++) {
#pragma unroll
        for (int nf = 0; nf < 4; nf++) {
            int n = n0 + wn * 32 + nf * 8 + qc * 2;
            float bv0 = bias[n], bv1 = bias[n + 1];
            int r0 = m0 + wm * 32 + mf * 16 + qr;
            float v00 = fmaxf(acc[mf][nf][0] + bv0, 0.0f);
            float v01 = fmaxf(acc[mf][nf][1] + bv1, 0.0f);
            float v10 = fmaxf(acc[mf][nf][2] + bv0, 0.0f);
            float v11 = fmaxf(acc[mf][nf][3] + bv1, 0.0f);
            if (FINAL) {
                *reinterpret_cast<float2*>(Of32 + (size_t)r0 * DOUT + n) =
                    make_float2(v00, v01);
                *reinterpret_cast<float2*>(Of32 + (size_t)(r0 + 8) * DOUT + n) =
                    make_float2(v10, v11);
            } else {
                uint32_t h0, l0, h1, l1;
                split2(v00, v01, h0, l0);
                split2(v10, v11, h1, l1);
                *reinterpret_cast<uint32_t*>(Ohi + (size_t)r0 * NH + n) = h0;
                *reinterpret_cast<uint32_t*>(Olo + (size_t)r0 * NH + n) = l0;
                *reinterpret_cast<uint32_t*>(Ohi + (size_t)(r0 + 8) * NH + n) = h1;
                *reinterpret_cast<uint32_t*>(Olo + (size_t)(r0 + 8) * NH + n) = l1;
            }
        }
    }
}

// ---------------- tail zero --------------------------------------------------
__global__ void zero_tail(float* out, size_t start, size_t count) {
    size_t i = (size_t)blockIdx.x * blockDim.x + threadIdx.x;
    if (i < count) out[start + i] = 0.0f;
}

// ---------------- launch -----------------------------------------------------
extern "C" void kernel_launch(void* const* d_in, const int* in_sizes, int n_in,
                              void* d_out, int out_size) {
    const float* x     = (const float*)d_in[0];
    const float* W_in  = (const float*)d_in[1];
    const float* b_in  = (const float*)d_in[2];
    const float* W_h   = (const float*)d_in[3];
    const float* b_h   = (const float*)d_in[4];
    const float* W_out = (const float*)d_in[5];
    const float* b_out = (const float*)d_in[6];
    float* out = (float*)d_out;

    __nv_bfloat16 *a0h, *a0l, *a1h, *a1l, *wih, *wil, *whh, *whl, *woh, *wol;
    cudaGetSymbolAddress((void**)&a0h, g_a0_hi);
    cudaGetSymbolAddress((void**)&a0l, g_a0_lo);
    cudaGetSymbolAddress((void**)&a1h, g_a1_hi);
    cudaGetSymbolAddress((void**)&a1l, g_a1_lo);
    cudaGetSymbolAddress((void**)&wih, g_win_hi);
    cudaGetSymbolAddress((void**)&wil, g_win_lo);
    cudaGetSymbolAddress((void**)&whh, g_wh_hi);
    cudaGetSymbolAddress((void**)&whl, g_wh_lo);
    cudaGetSymbolAddress((void**)&woh, g_wout_hi);
    cudaGetSymbolAddress((void**)&wol, g_wout_lo);

    cudaFuncSetAttribute(mlp_gemm<1, 0>, cudaFuncAttributeMaxDynamicSharedMemorySize,
                         3 * SM_STAGE);
    cudaFuncSetAttribute(mlp_gemm<0, 0>, cudaFuncAttributeMaxDynamicSharedMemorySize,
                         3 * SM_STAGE);
    cudaFuncSetAttribute(mlp_gemm<0, 1>, cudaFuncAttributeMaxDynamicSharedMemorySize,
                         3 * SM_STAGE);

    init_minmax<<<1, DIN>>>();
    colminmax<<<NROWS / 512, DIN>>>(x);
    discretize<<<NROWS / 512, DIN>>>(x);

    wprep<<<(DIN * NH + 255) / 256, 256>>>(W_in, wih, wil, NH, DIN);
    wprep<<<(NH * NH + 255) / 256, 256>>>(W_h, whh, whl, NH, NH);
    wprep<<<(NH * DOUT + 255) / 256, 256>>>(W_out, woh, wol, DOUT, NH);

    dim3 blk(512);
    dim3 gh(4, NROWS / 128);   // hidden: N=512 -> 4 n-tiles
    dim3 gf(1, NROWS / 128);   // final:  N=128 -> 1 n-tile
    const size_t smem = 3 * SM_STAGE;

    // L1: A exact (ints), 2 terms
    mlp_gemm<1, 0><<<gh, blk, smem>>>(a0h, nullptr, wih, wil, b_in, a1h, a1l, nullptr);
    // L2..L6: shared W_h, ping-pong, 3 terms
    mlp_gemm<0, 0><<<gh, blk, smem>>>(a1h, a1l, whh, whl, b_h, a0h, a0l, nullptr);
    mlp_gemm<0, 0><<<gh, blk, smem>>>(a0h, a0l, whh, whl, b_h, a1h, a1l, nullptr);
    mlp_gemm<0, 0><<<gh, blk, smem>>>(a1h, a1l, whh, whl, b_h, a0h, a0l, nullptr);
    mlp_gemm<0, 0><<<gh, blk, smem>>>(a0h, a0l, whh, whl, b_h, a1h, a1l, nullptr);
    mlp_gemm<0, 0><<<gh, blk, smem>>>(a1h, a1l, whh, whl, b_h, a0h, a0l, nullptr);
    // L7: final, fp32 out
    mlp_gemm<0, 1><<<gf, blk, smem>>>(a0h, a0l, woh, wol, b_out, nullptr, nullptr, out);

    size_t y_elems = (size_t)NROWS * DOUT;
    if ((size_t)out_size > y_elems) {
        size_t cnt = (size_t)out_size - y_elems;
        zero_tail<<<(unsigned)((cnt + 255) / 256), 256>>>(out, y_elems, cnt);
    }
}

// round 9
// speedup vs baseline: 2.3570x; 1.0003x over previous
#include <cuda_runtime.h>
#include <cuda_bf16.h>
#include <cstdint>

#define NROWS 131072
#define DIN   512
#define NH    512
#define DOUT  128
#define NBOUNDS 24

// ---------------- device scratch (plain row-major planes) -------------------
__device__ __align__(256) __nv_bfloat16 g_a0_hi[(size_t)NROWS * NH];
__device__ __align__(256) __nv_bfloat16 g_a0_lo[(size_t)NROWS * NH];
__device__ __align__(256) __nv_bfloat16 g_a1_hi[(size_t)NROWS * NH];
__device__ __align__(256) __nv_bfloat16 g_a1_lo[(size_t)NROWS * NH];
// weights transposed: [N][K]
__device__ __align__(256) __nv_bfloat16 g_win_hi[NH * DIN],  g_win_lo[NH * DIN];
__device__ __align__(256) __nv_bfloat16 g_wh_hi[NH * NH],    g_wh_lo[NH * NH];
__device__ __align__(256) __nv_bfloat16 g_wout_hi[DOUT * NH], g_wout_lo[DOUT * NH];
__device__ unsigned g_min_enc[DIN];
__device__ unsigned g_max_enc[DIN];

// ---------------- helpers ----------------------------------------------------
__device__ __forceinline__ uint32_t smem_u32(const void* p) {
    uint32_t a;
    asm("{ .reg .u64 t; cvta.to.shared.u64 t, %1; cvt.u32.u64 %0, t; }"
        : "=r"(a) : "l"(p));
    return a;
}
__device__ __forceinline__ void ldsm4(uint32_t* r, uint32_t a) {
    asm volatile("ldmatrix.sync.aligned.m8n8.x4.shared.b16 {%0,%1,%2,%3}, [%4];"
                 : "=r"(r[0]), "=r"(r[1]), "=r"(r[2]), "=r"(r[3]) : "r"(a));
}
__device__ __forceinline__ void mma16816(float* d, const uint32_t* a,
                                         uint32_t b0, uint32_t b1) {
    asm volatile(
        "mma.sync.aligned.m16n8k16.row.col.f32.bf16.bf16.f32 "
        "{%0,%1,%2,%3}, {%4,%5,%6,%7}, {%8,%9}, {%0,%1,%2,%3};"
        : "+f"(d[0]), "+f"(d[1]), "+f"(d[2]), "+f"(d[3])
        : "r"(a[0]), "r"(a[1]), "r"(a[2]), "r"(a[3]), "r"(b0), "r"(b1));
}
#define CP_ASYNC16(dst, src) \
    asm volatile("cp.async.cg.shared.global [%0], [%1], 16;" :: "r"(dst), "l"(src))
#define CP_COMMIT() asm volatile("cp.async.commit_group;" ::: "memory")
#define CP_WAIT2()  asm volatile("cp.async.wait_group 2;" ::: "memory")

__device__ __forceinline__ void split2(float a, float b, uint32_t& hi, uint32_t& lo) {
    __nv_bfloat16 ha = __float2bfloat16_rn(a), hb = __float2bfloat16_rn(b);
    __nv_bfloat16 la = __float2bfloat16_rn(a - __bfloat162float(ha));
    __nv_bfloat16 lb = __float2bfloat16_rn(b - __bfloat162float(hb));
    unsigned short uha = *reinterpret_cast<unsigned short*>(&ha);
    unsigned short uhb = *reinterpret_cast<unsigned short*>(&hb);
    unsigned short ula = *reinterpret_cast<unsigned short*>(&la);
    unsigned short ulb = *reinterpret_cast<unsigned short*>(&lb);
    hi = (uint32_t)uha | ((uint32_t)uhb << 16);
    lo = (uint32_t)ula | ((uint32_t)ulb << 16);
}

// ---------------- min/max + discretize ---------------------------------------
__device__ __forceinline__ unsigned enc_f(float f) {
    unsigned u = __float_as_uint(f);
    return (u & 0x80000000u) ? ~u : (u | 0x80000000u);
}
__device__ __forceinline__ float dec_f(unsigned e) {
    unsigned u = (e & 0x80000000u) ? (e & 0x7FFFFFFFu) : ~e;
    return __uint_as_float(u);
}
__global__ void init_minmax() {
    int i = threadIdx.x;
    g_min_enc[i] = 0xFFFFFFFFu;
    g_max_enc[i] = 0x00000000u;
}
__global__ void colminmax(const float* __restrict__ x) {
    const int col = threadIdx.x;
    const size_t base = (size_t)blockIdx.x * 512 * DIN + col;
    float v0 = x[base];
    float mn = v0, mx = v0;
    for (int r = 1; r < 512; r++) {
        float v = x[base + (size_t)r * DIN];
        mn = fminf(mn, v);
        mx = fmaxf(mx, v);
    }
    atomicMin(&g_min_enc[col], enc_f(mn));
    atomicMax(&g_max_enc[col], enc_f(mx));
}
__global__ void discretize(const float* __restrict__ x) {
    const int col = threadIdx.x;
    const float bmin = dec_f(g_min_enc[col]);
    const float bmax = dec_f(g_max_enc[col]);
    const float range = __fsub_rn(bmax, bmin);
    float bounds[NBOUNDS];
#pragma unroll
    for (int k = 0; k < NBOUNDS; k++) {
        float frac = __fdiv_rn((float)(k + 1), 25.0f);
        bounds[k] = __fadd_rn(bmin, __fmul_rn(range, frac));
    }
    const size_t base = (size_t)blockIdx.x * 512 * DIN + col;
    for (int r = 0; r < 512; r++) {
        float v = x[base + (size_t)r * DIN];
        int idx = 0;
#pragma unroll
        for (int k = 0; k < NBOUNDS; k++) idx += (bounds[k] < v) ? 1 : 0;
        g_a0_hi[base + (size_t)r * DIN] = __float2bfloat16_rn((float)idx);
    }
}

// ---------------- weight split + transpose ----------------------------------
__global__ void wprep(const float* __restrict__ W, __nv_bfloat16* __restrict__ hi,
                      __nv_bfloat16* __restrict__ lo, int N, int K) {
    int i = blockIdx.x * blockDim.x + threadIdx.x;
    if (i >= N * K) return;
    int k = i / N, n = i % N;  // W is [K][N]
    float w = W[i];
    __nv_bfloat16 h = __float2bfloat16_rn(w);
    __nv_bfloat16 l = __float2bfloat16_rn(w - __bfloat162float(h));
    hi[(size_t)n * K + k] = h;  // transposed [N][K]
    lo[(size_t)n * K + k] = l;
}

// ---------------- bf16 split-precision GEMM (mma.sync HMMA) -----------------
// BM=64, BN=128, 256 threads (2m x 4n warps, warp tile 32x32).
// 2 SMEM buffers of BK=64 loaded/consumed in BK=32 halves -> 4 half-stage
// pipeline, 96KB/CTA -> 2 CTAs per SM for barrier/epilogue overlap.
#define BUFSZ 49152
#define SM_AH 0
#define SM_AL 8192
#define SM_BH 16384
#define SM_BL 32768

template <int AEXACT, int FINAL>
__global__ __launch_bounds__(256, 2)
void mlp_gemm(const __nv_bfloat16* __restrict__ Ahi, const __nv_bfloat16* __restrict__ Alo,
              const __nv_bfloat16* __restrict__ Bhi, const __nv_bfloat16* __restrict__ Blo,
              const float* __restrict__ bias,
              __nv_bfloat16* __restrict__ Ohi, __nv_bfloat16* __restrict__ Olo,
              float* __restrict__ Of32) {
    extern __shared__ __align__(1024) unsigned char sm[];
    const uint32_t smb = smem_u32(sm);
    const int tid = threadIdx.x;
    const int lane = tid & 31, wid = tid >> 5;
    const int wm = wid >> 2, wn = wid & 3;      // 2 x 4 warp grid
    const int m0 = blockIdx.y * 64;
    const int n0 = blockIdx.x * 128;

    float acc[2][4][4];                         // mf(16 rows) x nf(8 cols) x quad
#pragma unroll
    for (int i = 0; i < 2; i++)
#pragma unroll
        for (int j = 0; j < 4; j++)
#pragma unroll
            for (int q = 0; q < 4; q++) acc[i][j][q] = 0.0f;

    // ---- half-stage loader: BK=32 slab into half (ch&1) of buffer ----------
    const int lr4 = tid >> 2, lc4 = tid & 3;    // 16B chunk coords
    auto load_half = [&](int ch) {
        const uint32_t sb = smb + (((uint32_t)(ch & 3)) >> 1) * BUFSZ;
        const int h4 = (ch & 1) * 4;
        const int k0 = ch * 32;
        {   // A planes: 64 rows x 4 chunks
            int r = lr4 & 63;                   // lr4 in 0..63
            uint32_t slot = (uint32_t)((h4 + lc4) ^ (r & 7)) << 4;
            CP_ASYNC16(sb + SM_AH + r * 128 + slot,
                       Ahi + (size_t)(m0 + r) * 512 + k0 + lc4 * 8);
            if (!AEXACT)
                CP_ASYNC16(sb + SM_AL + r * 128 + slot,
                           Alo + (size_t)(m0 + r) * 512 + k0 + lc4 * 8);
        }
#pragma unroll
        for (int it = 0; it < 2; it++) {        // B planes: 128 rows x 4 chunks
            int r = lr4 + it * 64;
            uint32_t slot = (uint32_t)((h4 + lc4) ^ (r & 7)) << 4;
            CP_ASYNC16(sb + SM_BH + r * 128 + slot,
                       Bhi + (size_t)(n0 + r) * 512 + k0 + lc4 * 8);
            CP_ASYNC16(sb + SM_BL + r * 128 + slot,
                       Blo + (size_t)(n0 + r) * 512 + k0 + lc4 * 8);
        }
    };

    const int arow = lane & 15;   // row within 16-row fragment
    const int kbl  = lane >> 4;   // k-half selector

    // precomputed per-fragment row offsets
    uint32_t aoff[2], boff[2];
    int amod[2], bmod[2];
#pragma unroll
    for (int mf = 0; mf < 2; mf++) {
        int r = wm * 32 + mf * 16 + arow;       // 0..63
        aoff[mf] = r * 128; amod[mf] = r & 7;
    }
#pragma unroll
    for (int g = 0; g < 2; g++) {
        int r = wn * 32 + g * 16 + arow;        // 0..127
        boff[g] = r * 128; bmod[g] = r & 7;
    }

    load_half(0); CP_COMMIT();
    load_half(1); CP_COMMIT();
    load_half(2); CP_COMMIT();

#pragma unroll 1
    for (int ch = 0; ch < 16; ch++) {
        CP_WAIT2();
        __syncthreads();
        if (ch + 3 < 16) load_half(ch + 3);
        CP_COMMIT();

        const uint32_t sb = smb + (((uint32_t)(ch & 3)) >> 1) * BUFSZ;
        const int h4 = (ch & 1) * 4;
#pragma unroll
        for (int kk = 0; kk < 2; kk++) {
            const int c = h4 + kk * 2 + kbl;
            uint32_t ah[2][4], al[2][4], bh[2][4], bl[2][4];
#pragma unroll
            for (int mf = 0; mf < 2; mf++) {
                uint32_t o = aoff[mf] + (uint32_t)((c ^ amod[mf]) << 4);
                ldsm4(ah[mf], sb + SM_AH + o);
                if (!AEXACT) ldsm4(al[mf], sb + SM_AL + o);
            }
#pragma unroll
            for (int g = 0; g < 2; g++) {
                uint32_t o = boff[g] + (uint32_t)((c ^ bmod[g]) << 4);
                ldsm4(bh[g], sb + SM_BH + o);
                ldsm4(bl[g], sb + SM_BL + o);
            }
#pragma unroll
            for (int g = 0; g < 2; g++)
#pragma unroll
                for (int mf = 0; mf < 2; mf++) {
                    mma16816(acc[mf][2 * g],     ah[mf], bh[g][0], bh[g][2]);
                    mma16816(acc[mf][2 * g + 1], ah[mf], bh[g][1], bh[g][3]);
                    mma16816(acc[mf][2 * g],     ah[mf], bl[g][0], bl[g][2]);
                    mma16816(acc[mf][2 * g + 1], ah[mf], bl[g][1], bl[g][3]);
                    if (!AEXACT) {
                        mma16816(acc[mf][2 * g],     al[mf], bh[g][0], bh[g][2]);
                        mma16816(acc[mf][2 * g + 1], al[mf], bh[g][1], bh[g][3]);
                    }
                }
        }
    }

    // ---- epilogue: bias + relu, split bf16 (hidden) or fp32 (final) ----
    const int qr = lane >> 2, qc = lane & 3;
#pragma unroll
    for (int mf = 0; mf < 2; mf++) {
#pragma unroll
        for (int nf = 0; nf < 4; nf++) {
            int n = n0 + wn * 32 + nf * 8 + qc * 2;
            float bv0 = bias[n], bv1 = bias[n + 1];
            int r0 = m0 + wm * 32 + mf * 16 + qr;
            float v00 = fmaxf(acc[mf][nf][0] + bv0, 0.0f);
            float v01 = fmaxf(acc[mf][nf][1] + bv1, 0.0f);
            float v10 = fmaxf(acc[mf][nf][2] + bv0, 0.0f);
            float v11 = fmaxf(acc[mf][nf][3] + bv1, 0.0f);
            if (FINAL) {
                *reinterpret_cast<float2*>(Of32 + (size_t)r0 * DOUT + n) =
                    make_float2(v00, v01);
                *reinterpret_cast<float2*>(Of32 + (size_t)(r0 + 8) * DOUT + n) =
                    make_float2(v10, v11);
            } else {
                uint32_t h0, l0, h1, l1;
                split2(v00, v01, h0, l0);
                split2(v10, v11, h1, l1);
                *reinterpret_cast<uint32_t*>(Ohi + (size_t)r0 * NH + n) = h0;
                *reinterpret_cast<uint32_t*>(Olo + (size_t)r0 * NH + n) = l0;
                *reinterpret_cast<uint32_t*>(Ohi + (size_t)(r0 + 8) * NH + n) = h1;
                *reinterpret_cast<uint32_t*>(Olo + (size_t)(r0 + 8) * NH + n) = l1;
            }
        }
    }
}

// ---------------- tail zero --------------------------------------------------
__global__ void zero_tail(float* out, size_t start, size_t count) {
    size_t i = (size_t)blockIdx.x * blockDim.x + threadIdx.x;
    if (i < count) out[start + i] = 0.0f;
}

// ---------------- launch -----------------------------------------------------
extern "C" void kernel_launch(void* const* d_in, const int* in_sizes, int n_in,
                              void* d_out, int out_size) {
    const float* x     = (const float*)d_in[0];
    const float* W_in  = (const float*)d_in[1];
    const float* b_in  = (const float*)d_in[2];
    const float* W_h   = (const float*)d_in[3];
    const float* b_h   = (const float*)d_in[4];
    const float* W_out = (const float*)d_in[5];
    const float* b_out = (const float*)d_in[6];
    float* out = (float*)d_out;

    __nv_bfloat16 *a0h, *a0l, *a1h, *a1l, *wih, *wil, *whh, *whl, *woh, *wol;
    cudaGetSymbolAddress((void**)&a0h, g_a0_hi);
    cudaGetSymbolAddress((void**)&a0l, g_a0_lo);
    cudaGetSymbolAddress((void**)&a1h, g_a1_hi);
    cudaGetSymbolAddress((void**)&a1l, g_a1_lo);
    cudaGetSymbolAddress((void**)&wih, g_win_hi);
    cudaGetSymbolAddress((void**)&wil, g_win_lo);
    cudaGetSymbolAddress((void**)&whh, g_wh_hi);
    cudaGetSymbolAddress((void**)&whl, g_wh_lo);
    cudaGetSymbolAddress((void**)&woh, g_wout_hi);
    cudaGetSymbolAddress((void**)&wol, g_wout_lo);

    const size_t smem = 2 * BUFSZ;  // 96KB per CTA
    cudaFuncSetAttribute(mlp_gemm<1, 0>, cudaFuncAttributeMaxDynamicSharedMemorySize, smem);
    cudaFuncSetAttribute(mlp_gemm<0, 0>, cudaFuncAttributeMaxDynamicSharedMemorySize, smem);
    cudaFuncSetAttribute(mlp_gemm<0, 1>, cudaFuncAttributeMaxDynamicSharedMemorySize, smem);

    init_minmax<<<1, DIN>>>();
    colminmax<<<NROWS / 512, DIN>>>(x);
    discretize<<<NROWS / 512, DIN>>>(x);

    wprep<<<(DIN * NH + 255) / 256, 256>>>(W_in, wih, wil, NH, DIN);
    wprep<<<(NH * NH + 255) / 256, 256>>>(W_h, whh, whl, NH, NH);
    wprep<<<(NH * DOUT + 255) / 256, 256>>>(W_out, woh, wol, DOUT, NH);

    dim3 blk(256);
    dim3 gh(4, NROWS / 64);    // hidden: N=512 -> 4 n-tiles, 2048 m-tiles
    dim3 gf(1, NROWS / 64);    // final:  N=128 -> 1 n-tile

    // L1: A exact (ints), 2 terms
    mlp_gemm<1, 0><<<gh, blk, smem>>>(a0h, nullptr, wih, wil, b_in, a1h, a1l, nullptr);
    // L2..L6: shared W_h, ping-pong, 3 terms
    mlp_gemm<0, 0><<<gh, blk, smem>>>(a1h, a1l, whh, whl, b_h, a0h, a0l, nullptr);
    mlp_gemm<0, 0><<<gh, blk, smem>>>(a0h, a0l, whh, whl, b_h, a1h, a1l, nullptr);
    mlp_gemm<0, 0><<<gh, blk, smem>>>(a1h, a1l, whh, whl, b_h, a0h, a0l, nullptr);
    mlp_gemm<0, 0><<<gh, blk, smem>>>(a0h, a0l, whh, whl, b_h, a1h, a1l, nullptr);
    mlp_gemm<0, 0><<<gh, blk, smem>>>(a1h, a1l, whh, whl, b_h, a0h, a0l, nullptr);
    // L7: final, fp32 out
    mlp_gemm<0, 1><<<gf, blk, smem>>>(a0h, a0l, woh, wol, b_out, nullptr, nullptr, out);

    size_t y_elems = (size_t)NROWS * DOUT;
    if ((size_t)out_size > y_elems) {
        size_t cnt = (size_t)out_size - y_elems;
        zero_tail<<<(unsigned)((cnt + 255) / 256), 256>>>(out, y_elems, cnt);
    }
}